// round 15
// baseline (speedup 1.0000x reference)
#include <cuda_runtime.h>
#include <cuda_fp16.h>
#include <cstdint>
#include <cstddef>
#include <math.h>
#include <float.h>

typedef unsigned int u32;

#define BB 2
#define SS 2048
#define DIM 4096
#define NH 32
#define NKV 8
#define HD 128
#define NREP 4
#define M_TOK (BB*SS)
#define KVDIM (NKV*HD)

// ---------------- scratch (allocation-free device globals) ----------------
__device__ __half g_xh[(size_t)M_TOK * DIM];
__device__ __half g_wq[(size_t)DIM * DIM],    g_wo[(size_t)DIM * DIM];
__device__ __half g_wk[(size_t)KVDIM * DIM],  g_wv[(size_t)KVDIM * DIM];
__device__ __half g_qh[(size_t)M_TOK * DIM];
__device__ __half g_kh[(size_t)M_TOK * KVDIM];
__device__ __half g_vh[(size_t)M_TOK * KVDIM];
__device__ __half g_ah[(size_t)M_TOK * DIM];

// ---------------------------------------------------------------------------
// prep: fp32 -> fp16, 4 independent float4 per thread (MLP=4)
// ---------------------------------------------------------------------------
__global__ void prep_half(const float* __restrict__ wq, const float* __restrict__ wk,
                          const float* __restrict__ wv, const float* __restrict__ wo,
                          const float* __restrict__ x,
                          __half* __restrict__ owq, __half* __restrict__ owk,
                          __half* __restrict__ owv, __half* __restrict__ owo,
                          __half* __restrict__ ox)
{
    const size_t NW = (size_t)DIM * DIM;
    const size_t NK = (size_t)KVDIM * DIM;
    const size_t NX = (size_t)M_TOK * DIM;
    size_t i = ((size_t)blockIdx.x * blockDim.x + threadIdx.x) * 16;
    const float* src; __half* dst; size_t off;
    if      (i < NW)                    { src = wq; dst = owq; off = i; }
    else if (i < NW + NK)               { src = wk; dst = owk; off = i - NW; }
    else if (i < NW + 2 * NK)           { src = wv; dst = owv; off = i - NW - NK; }
    else if (i < 2 * NW + 2 * NK)       { src = wo; dst = owo; off = i - NW - 2 * NK; }
    else if (i < 2 * NW + 2 * NK + NX)  { src = x;  dst = ox;  off = i - 2 * NW - 2 * NK; }
    else return;
    float4 v0 = *(const float4*)&src[off];
    float4 v1 = *(const float4*)&src[off + 4];
    float4 v2 = *(const float4*)&src[off + 8];
    float4 v3 = *(const float4*)&src[off + 12];
    *(__half2*)&dst[off]      = __floats2half2_rn(v0.x, v0.y);
    *(__half2*)&dst[off + 2]  = __floats2half2_rn(v0.z, v0.w);
    *(__half2*)&dst[off + 4]  = __floats2half2_rn(v1.x, v1.y);
    *(__half2*)&dst[off + 6]  = __floats2half2_rn(v1.z, v1.w);
    *(__half2*)&dst[off + 8]  = __floats2half2_rn(v2.x, v2.y);
    *(__half2*)&dst[off + 10] = __floats2half2_rn(v2.z, v2.w);
    *(__half2*)&dst[off + 12] = __floats2half2_rn(v3.x, v3.y);
    *(__half2*)&dst[off + 14] = __floats2half2_rn(v3.z, v3.w);
}

// ---------------------------------------------------------------------------
// common PTX helpers
// ---------------------------------------------------------------------------
__device__ __forceinline__ void cpasync16(const void* s, const void* g) {
    u32 sa = (u32)__cvta_generic_to_shared(s);
    asm volatile("cp.async.cg.shared.global [%0], [%1], 16;\n" :: "r"(sa), "l"(g));
}
__device__ __forceinline__ void ldsm4(u32& r0, u32& r1, u32& r2,
                                      u32& r3, const void* p) {
    u32 a = (u32)__cvta_generic_to_shared(p);
    asm volatile("ldmatrix.sync.aligned.m8n8.x4.shared.b16 {%0,%1,%2,%3}, [%4];"
                 : "=r"(r0), "=r"(r1), "=r"(r2), "=r"(r3) : "r"(a));
}
__device__ __forceinline__ void ldsm4t(u32& r0, u32& r1, u32& r2,
                                       u32& r3, const void* p) {
    u32 a = (u32)__cvta_generic_to_shared(p);
    asm volatile("ldmatrix.sync.aligned.m8n8.x4.trans.shared.b16 {%0,%1,%2,%3}, [%4];"
                 : "=r"(r0), "=r"(r1), "=r"(r2), "=r"(r3) : "r"(a));
}
__device__ __forceinline__ void mma16816h(float* c, const u32* a, const u32* b) {
    asm volatile(
        "mma.sync.aligned.m16n8k16.row.col.f32.f16.f16.f32 "
        "{%0,%1,%2,%3}, {%4,%5,%6,%7}, {%8,%9}, {%0,%1,%2,%3};"
        : "+f"(c[0]), "+f"(c[1]), "+f"(c[2]), "+f"(c[3])
        : "r"(a[0]), "r"(a[1]), "r"(a[2]), "r"(a[3]), "r"(b[0]), "r"(b[1]));
}
__device__ __forceinline__ u32 pack_h2(float a, float b) {
    __half2 h = __floats2half2_rn(a, b);
    return *(u32*)&h;
}

// ---------------------------------------------------------------------------
// GEMM mainloop (round-10 config, verbatim): 128x128 tile, BK=64,
// 256 threads = 8 warps (2x4), warp tile 64x32, 2-stage cp.async.
// ---------------------------------------------------------------------------
#define KSTR 72
#define KTILE (128*KSTR)
#define GEMM_SMEM (2 * 2 * KTILE * 2)    // 73728 bytes

__device__ __forceinline__ void load_stage(
    __half* sb, const __half* __restrict__ A, const __half* __restrict__ Bm,
    int tid, int m0, int n0, int K, int k0)
{
#pragma unroll
    for (int i = 0; i < 4; i++) {
        int c = tid + i * 256;           // 0..1023
        int row = c >> 3;
        int ch  = (c & 7) * 8;
        cpasync16(&sb[row * KSTR + ch],         &A[(size_t)(m0 + row) * K + k0 + ch]);
        cpasync16(&sb[KTILE + row * KSTR + ch], &Bm[(size_t)(n0 + row) * K + k0 + ch]);
    }
    asm volatile("cp.async.commit_group;");
}

__device__ __forceinline__ void gemm_mainloop(
    __half* smem, float acc[4][4][4],
    const __half* __restrict__ A, const __half* __restrict__ Bm,
    int tid, int lane, int wm, int wn, int m0, int n0, int K)
{
    const int KT = K / 64;
    load_stage(smem, A, Bm, tid, m0, n0, K, 0);
    asm volatile("cp.async.wait_group 0;");
    __syncthreads();

    for (int kt = 0; kt < KT; kt++) {
        int cur = kt & 1;
        if (kt + 1 < KT)
            load_stage(smem + (cur ^ 1) * 2 * KTILE, A, Bm, tid, m0, n0, K, (kt + 1) * 64);

        const __half* sA = smem + cur * 2 * KTILE;
        const __half* sB = sA + KTILE;

#pragma unroll
        for (int kk = 0; kk < 64; kk += 16) {
            u32 ah[4][4], bb[4][2];
            int arow = wm * 64 + (lane & 7) + ((lane >> 3) & 1) * 8;
            int acol = kk + ((lane >> 4) & 1) * 8;
#pragma unroll
            for (int mt = 0; mt < 4; mt++)
                ldsm4(ah[mt][0], ah[mt][1], ah[mt][2], ah[mt][3],
                      sA + (arow + mt * 16) * KSTR + acol);
            int brow = wn * 32 + (lane & 7) + ((lane >> 4) & 1) * 8;
            int bcol = kk + ((lane >> 3) & 1) * 8;
#pragma unroll
            for (int p = 0; p < 2; p++) {
                u32 r0, r1, r2, r3;
                ldsm4(r0, r1, r2, r3, sB + (brow + p * 16) * KSTR + bcol);
                bb[2 * p][0] = r0; bb[2 * p][1] = r1;
                bb[2 * p + 1][0] = r2; bb[2 * p + 1][1] = r3;
            }
#pragma unroll
            for (int mt = 0; mt < 4; mt++)
#pragma unroll
                for (int nt = 0; nt < 4; nt++)
                    mma16816h(acc[mt][nt], ah[mt], bb[nt]);
        }
        asm volatile("cp.async.wait_group 0;");
        __syncthreads();
    }
}

// ---------------------------------------------------------------------------
// fused QKV GEMM (single-pass fp16) + RoPE epilogue. grid: (48, M/128), 256 thr
// ---------------------------------------------------------------------------
__global__ __launch_bounds__(256, 2) void gemm_qkv(
    const __half* __restrict__ A,
    const __half* __restrict__ Wq, const __half* __restrict__ Wk,
    const __half* __restrict__ Wv,
    __half* __restrict__ qh, __half* __restrict__ kh, __half* __restrict__ vh,
    const float* __restrict__ fc, const float* __restrict__ fs)
{
    extern __shared__ __half smem[];
    int tid = threadIdx.x;
    int lane = tid & 31, wid = tid >> 5;
    int wm = wid & 1, wn = wid >> 1;
    int m0 = blockIdx.y * 128;

    int bx = blockIdx.x;
    int seg = (bx < 32) ? 0 : ((bx < 40) ? 1 : 2);
    int bn0 = (seg == 0) ? bx * 128 : ((seg == 1) ? (bx - 32) * 128 : (bx - 40) * 128);
    const __half* Bm = (seg == 0) ? Wq : ((seg == 1) ? Wk : Wv);
    int Nout = (seg == 0) ? DIM : KVDIM;

    float acc[4][4][4];
#pragma unroll
    for (int i = 0; i < 4; i++)
#pragma unroll
        for (int j = 0; j < 4; j++)
#pragma unroll
            for (int k = 0; k < 4; k++) acc[i][j][k] = 0.f;

    gemm_mainloop(smem, acc, A, Bm, tid, lane, wm, wn, m0, bn0, DIM);

    const float scale = 0.08838834764831845f;

#pragma unroll
    for (int mt = 0; mt < 4; mt++) {
#pragma unroll
        for (int nt = 0; nt < 4; nt++) {
            int r  = m0 + wm * 64 + mt * 16 + (lane >> 2);
            int cl = bn0 + wn * 32 + nt * 8 + (lane & 3) * 2;
            float a0 = acc[mt][nt][0], a1 = acc[mt][nt][1];
            float a2 = acc[mt][nt][2], a3 = acc[mt][nt][3];
            size_t o0 = (size_t)r * Nout + cl;
            size_t o1 = (size_t)(r + 8) * Nout + cl;

            if (seg == 2) {
                *(u32*)&vh[o0] = pack_h2(a0, a1);
                *(u32*)&vh[o1] = pack_h2(a2, a3);
            } else {
                int p  = (cl & 127) >> 1;
                int s0 = r & (SS - 1), s1 = (r + 8) & (SS - 1);
                float c0f = fc[s0 * 64 + p], sn0 = fs[s0 * 64 + p];
                float c1f = fc[s1 * 64 + p], sn1 = fs[s1 * 64 + p];
                float r0 = a0 * c0f - a1 * sn0, i0 = a0 * sn0 + a1 * c0f;
                float r1 = a2 * c1f - a3 * sn1, i1 = a2 * sn1 + a3 * c1f;
                if (seg == 0) {
                    r0 *= scale; i0 *= scale; r1 *= scale; i1 *= scale;
                    *(u32*)&qh[o0] = pack_h2(r0, i0);
                    *(u32*)&qh[o1] = pack_h2(r1, i1);
                } else {
                    *(u32*)&kh[o0] = pack_h2(r0, i0);
                    *(u32*)&kh[o1] = pack_h2(r1, i1);
                }
            }
        }
    }
}

// ---------------------------------------------------------------------------
// wo GEMM (single-pass fp16 A), fp32 out. (round-10 verbatim)
// ---------------------------------------------------------------------------
__global__ __launch_bounds__(256, 2) void gemm_wo(
    const __half* __restrict__ A, const __half* __restrict__ Bm,
    float* __restrict__ C, int N, int K)
{
    extern __shared__ __half smem[];
    int tid = threadIdx.x;
    int lane = tid & 31, wid = tid >> 5;
    int wm = wid & 1, wn = wid >> 1;
    int m0 = blockIdx.y * 128, n0 = blockIdx.x * 128;

    float acc[4][4][4];
#pragma unroll
    for (int i = 0; i < 4; i++)
#pragma unroll
        for (int j = 0; j < 4; j++)
#pragma unroll
            for (int k = 0; k < 4; k++) acc[i][j][k] = 0.f;

    gemm_mainloop(smem, acc, A, Bm, tid, lane, wm, wn, m0, n0, K);

#pragma unroll
    for (int mt = 0; mt < 4; mt++) {
#pragma unroll
        for (int nt = 0; nt < 4; nt++) {
            int r = m0 + wm * 64 + mt * 16 + (lane >> 2);
            int c = n0 + wn * 32 + nt * 8 + (lane & 3) * 2;
            *(float2*)&C[(size_t)r * N + c] =
                make_float2(acc[mt][nt][0], acc[mt][nt][1]);
            *(float2*)&C[(size_t)(r + 8) * N + c] =
                make_float2(acc[mt][nt][2], acc[mt][nt][3]);
        }
    }
}

// ---------------------------------------------------------------------------
// fast exp on the FMA pipe
// ---------------------------------------------------------------------------
__device__ __forceinline__ float fast_exp(float x) {
    x = fmaxf(x, -87.f);
    float z = x * 1.4426950408889634f;
    float t = z + 12582912.f;
    int   e = __float_as_int(t) << 23;
    float n = t - 12582912.f;
    float f = z - n;
    float p = 1.3387706e-3f;
    p = fmaf(p, f, 9.6181291e-3f);
    p = fmaf(p, f, 5.5504108e-2f);
    p = fmaf(p, f, 2.4022650e-1f);
    p = fmaf(p, f, 6.9314718e-1f);
    p = fmaf(p, f, 1.0f);
    return __int_as_float(__float_as_int(p) + e);
}

// ---------------------------------------------------------------------------
// Tensor-core flash attention: single-pass S, fp16 P@V, fp16 out.
// BM=128 (8 warps x 16 rows), BN=64, 256 threads. smem 69632 B.
// ---------------------------------------------------------------------------
#define FSTR 136
#define FA2_TILE (64 * FSTR)
#define FA2_SMEM (4 * FA2_TILE * 2)   // Q(2 tiles) + K + V = 69632 B

__global__ __launch_bounds__(256) void flash_mma(
    const __half* __restrict__ qh, const __half* __restrict__ kh,
    const __half* __restrict__ vv, __half* __restrict__ outh)
{
    extern __shared__ __half sm2[];
    __half* sqh = sm2;                    // 128 rows
    __half* skh = sqh + 2 * FA2_TILE;     // 64 rows
    __half* sv  = skh + FA2_TILE;         // 64 rows

    int tid = threadIdx.x, lane = tid & 31, wid = tid >> 5;
    int qt = gridDim.x - 1 - blockIdx.x;   // heavy blocks first
    int bh = blockIdx.y;
    int b = bh >> 5, h = bh & 31, kvh = h >> 2;
    int q0 = qt * 128;

    // load Q tile: 128 rows x 16 int4 = 2048 int4
#pragma unroll
    for (int i = 0; i < 8; i++) {
        int c = tid + i * 256;
        int row = c >> 4;
        int col = (c & 15) * 8;
        size_t g = ((size_t)(b * SS + q0 + row) * NH + h) * HD + col;
        *(int4*)&sqh[row * FSTR + col] = *(const int4*)&qh[g];
    }

    float o[16][4];
#pragma unroll
    for (int n = 0; n < 16; n++)
#pragma unroll
        for (int j = 0; j < 4; j++) o[n][j] = 0.f;
    float m0 = -1e30f, m1 = -1e30f, l0 = 0.f, l1 = 0.f;

    int gr = lane >> 2, qc = (lane & 3) * 2;
    int arow = wid * 16 + (lane & 7) + ((lane >> 3) & 1) * 8;
    int acolo = ((lane >> 4) & 1) * 8;
    int brow = (lane & 7) + ((lane >> 4) & 1) * 8;
    int bcolo = ((lane >> 3) & 1) * 8;
    int vrow = (lane & 7) + ((lane >> 3) & 1) * 8;
    int vcolo = ((lane >> 4) & 1) * 8;

    const int NT = 2 * qt + 2;            // tiles covering cols [0, q0+128)
    for (int nt = 0; nt < NT; nt++) {
        int k0 = nt * 64;
        __syncthreads();
        // load K,V tiles: 64 rows x 16 int4 = 1024 int4 over 256 threads
#pragma unroll
        for (int i = 0; i < 4; i++) {
            int c = tid + i * 256;
            int row = c >> 4;
            int col = (c & 15) * 8;
            size_t g = ((size_t)(b * SS + k0 + row) * NKV + kvh) * HD + col;
            *(int4*)&skh[row * FSTR + col] = *(const int4*)&kh[g];
            *(int4*)&sv [row * FSTR + col] = *(const int4*)&vv[g];
        }
        __syncthreads();

        // warps whose 16 rows are entirely above the diagonal: skip compute
        // (rows q0+wid*16 .. +15; fully masked iff k0 > q0 + wid*16 + 15)
        if (k0 > q0 + wid * 16 + 15) continue;

        float s[8][4];
#pragma unroll
        for (int n = 0; n < 8; n++)
#pragma unroll
            for (int j = 0; j < 4; j++) s[n][j] = 0.f;

#pragma unroll
        for (int kc = 0; kc < 8; kc++) {
            u32 aH[4];
            ldsm4(aH[0], aH[1], aH[2], aH[3], &sqh[arow * FSTR + kc * 16 + acolo]);
            u32 bH[8][2];
#pragma unroll
            for (int p = 0; p < 4; p++) {
                u32 r0, r1, r2, r3;
                ldsm4(r0, r1, r2, r3, &skh[(p * 16 + brow) * FSTR + kc * 16 + bcolo]);
                bH[2 * p][0] = r0; bH[2 * p][1] = r1;
                bH[2 * p + 1][0] = r2; bH[2 * p + 1][1] = r3;
            }
#pragma unroll
            for (int n = 0; n < 8; n++) mma16816h(s[n], aH, bH[n]);
        }

        // causal mask on tiles that touch the diagonal
        if (k0 + 63 > q0 + wid * 16) {
            int lr0 = q0 + wid * 16 + gr, lr1 = lr0 + 8;
#pragma unroll
            for (int n = 0; n < 8; n++) {
                int lc = k0 + n * 8 + qc;
                if (lc     > lr0) s[n][0] = -1e30f;
                if (lc + 1 > lr0) s[n][1] = -1e30f;
                if (lc     > lr1) s[n][2] = -1e30f;
                if (lc + 1 > lr1) s[n][3] = -1e30f;
            }
        }

        float mx0 = -1e30f, mx1 = -1e30f;
#pragma unroll
        for (int n = 0; n < 8; n++) {
            mx0 = fmaxf(mx0, fmaxf(s[n][0], s[n][1]));
            mx1 = fmaxf(mx1, fmaxf(s[n][2], s[n][3]));
        }
        mx0 = fmaxf(mx0, __shfl_xor_sync(0xffffffffu, mx0, 1));
        mx0 = fmaxf(mx0, __shfl_xor_sync(0xffffffffu, mx0, 2));
        mx1 = fmaxf(mx1, __shfl_xor_sync(0xffffffffu, mx1, 1));
        mx1 = fmaxf(mx1, __shfl_xor_sync(0xffffffffu, mx1, 2));
        float nm0 = fmaxf(m0, mx0), nm1 = fmaxf(m1, mx1);
        float a0 = fast_exp(m0 - nm0), a1 = fast_exp(m1 - nm1);
        m0 = nm0; m1 = nm1;

        float ls0 = 0.f, ls1 = 0.f;
        u32 pa[4][4];
#pragma unroll
        for (int n = 0; n < 8; n++) {
            float p0 = fast_exp(s[n][0] - nm0);
            float p1 = fast_exp(s[n][1] - nm0);
            float p2 = fast_exp(s[n][2] - nm1);
            float p3 = fast_exp(s[n][3] - nm1);
            ls0 += p0 + p1; ls1 += p2 + p3;
            __half2 hi = __floats2half2_rn(p0, p1);
            __half2 lo = __floats2half2_rn(p2, p3);
            int j = n >> 1;
            if ((n & 1) == 0) {
                pa[j][0] = *(u32*)&hi; pa[j][1] = *(u32*)&lo;
            } else {
                pa[j][2] = *(u32*)&hi; pa[j][3] = *(u32*)&lo;
            }
        }
        ls0 += __shfl_xor_sync(0xffffffffu, ls0, 1);
        ls0 += __shfl_xor_sync(0xffffffffu, ls0, 2);
        ls1 += __shfl_xor_sync(0xffffffffu, ls1, 1);
        ls1 += __shfl_xor_sync(0xffffffffu, ls1, 2);
        l0 = l0 * a0 + ls0;
        l1 = l1 * a1 + ls1;

#pragma unroll
        for (int n = 0; n < 16; n++) {
            o[n][0] *= a0; o[n][1] *= a0;
            o[n][2] *= a1; o[n][3] *= a1;
        }

#pragma unroll
        for (int np = 0; np < 8; np++) {
#pragma unroll
            for (int j = 0; j < 4; j++) {
                u32 r0, r1, r2, r3;
                ldsm4t(r0, r1, r2, r3, &sv[(j * 16 + vrow) * FSTR + np * 16 + vcolo]);
                u32 bv0[2] = {r0, r1};
                u32 bv1[2] = {r2, r3};
                mma16816h(o[2 * np],     pa[j], bv0);
                mma16816h(o[2 * np + 1], pa[j], bv1);
            }
        }
    }

    float inv0 = 1.f / l0, inv1 = 1.f / l1;
    int row0 = q0 + wid * 16 + gr;
#pragma unroll
    for (int n = 0; n < 16; n++) {
        int col = n * 8 + qc;
        size_t base0 = ((size_t)(b * SS + row0)     * NH + h) * HD + col;
        size_t base1 = ((size_t)(b * SS + row0 + 8) * NH + h) * HD + col;
        *(u32*)&outh[base0] = pack_h2(o[n][0] * inv0, o[n][1] * inv0);
        *(u32*)&outh[base1] = pack_h2(o[n][2] * inv1, o[n][3] * inv1);
    }
}

// ---------------------------------------------------------------------------
extern "C" void kernel_launch(void* const* d_in, const int* in_sizes, int n_in,
                              void* d_out, int out_size)
{
    const float* x   = (const float*)d_in[0];
    const float* wq  = (const float*)d_in[1];
    const float* wk  = (const float*)d_in[2];
    const float* wv  = (const float*)d_in[3];
    const float* wo  = (const float*)d_in[4];
    const float* fc  = (const float*)d_in[5];
    const float* fs  = (const float*)d_in[6];
    float* out = (float*)d_out;

    __half *xh, *wqf, *wkf, *wvf, *wof;
    cudaGetSymbolAddress((void**)&xh, g_xh);
    cudaGetSymbolAddress((void**)&wqf, g_wq);  cudaGetSymbolAddress((void**)&wkf, g_wk);
    cudaGetSymbolAddress((void**)&wvf, g_wv);  cudaGetSymbolAddress((void**)&wof, g_wo);
    __half *qhp, *khp, *vhp, *ahp;
    cudaGetSymbolAddress((void**)&qhp, g_qh);  cudaGetSymbolAddress((void**)&khp, g_kh);
    cudaGetSymbolAddress((void**)&vhp, g_vh);  cudaGetSymbolAddress((void**)&ahp, g_ah);

    cudaFuncSetAttribute(gemm_qkv, cudaFuncAttributeMaxDynamicSharedMemorySize, GEMM_SMEM);
    cudaFuncSetAttribute(gemm_wo, cudaFuncAttributeMaxDynamicSharedMemorySize, GEMM_SMEM);
    cudaFuncSetAttribute(flash_mma, cudaFuncAttributeMaxDynamicSharedMemorySize, FA2_SMEM);

    // prep: all weights + x -> fp16
    size_t total = 2 * (size_t)DIM * DIM + 2 * (size_t)KVDIM * DIM + (size_t)M_TOK * DIM;
    prep_half<<<(unsigned)(total / 16 / 256), 256>>>(wq, wk, wv, wo, x,
                                                     wqf, wkf, wvf, wof, xh);

    // fused QKV projection + RoPE (q, k, v all fp16)
    dim3 gqkv(48, M_TOK / 128);
    gemm_qkv<<<gqkv, 256, GEMM_SMEM>>>(xh, wqf, wkf, wvf, qhp, khp, vhp, fc, fs);

    // attention (single-pass S, BM=128, fp16 out)
    dim3 ga(SS / 128, BB * NH);
    flash_mma<<<ga, 256, FA2_SMEM>>>(qhp, khp, vhp, ahp);

    // output projection
    dim3 gq(DIM / 128, M_TOK / 128);
    gemm_wo<<<gq, 256, GEMM_SMEM>>>(ahp, wof, out, DIM, DIM);
}

// round 16
// speedup vs baseline: 1.0370x; 1.0370x over previous
#include <cuda_runtime.h>
#include <cuda_fp16.h>
#include <cstdint>
#include <cstddef>
#include <math.h>
#include <float.h>

typedef unsigned int u32;

#define BB 2
#define SS 2048
#define DIM 4096
#define NH 32
#define NKV 8
#define HD 128
#define NREP 4
#define M_TOK (BB*SS)
#define KVDIM (NKV*HD)

// ---------------- scratch (allocation-free device globals) ----------------
__device__ __half g_xh[(size_t)M_TOK * DIM];
__device__ __half g_wq[(size_t)DIM * DIM],    g_wo[(size_t)DIM * DIM];
__device__ __half g_wk[(size_t)KVDIM * DIM],  g_wv[(size_t)KVDIM * DIM];
__device__ __half g_qh[(size_t)M_TOK * DIM];
__device__ __half g_kh[(size_t)M_TOK * KVDIM];
__device__ __half g_vh[(size_t)M_TOK * KVDIM];
__device__ __half g_ah[(size_t)M_TOK * DIM];

// ---------------------------------------------------------------------------
// prep: fp32 -> fp16, 4 independent float4 per thread (MLP=4)
// ---------------------------------------------------------------------------
__global__ void prep_half(const float* __restrict__ wq, const float* __restrict__ wk,
                          const float* __restrict__ wv, const float* __restrict__ wo,
                          const float* __restrict__ x,
                          __half* __restrict__ owq, __half* __restrict__ owk,
                          __half* __restrict__ owv, __half* __restrict__ owo,
                          __half* __restrict__ ox)
{
    const size_t NW = (size_t)DIM * DIM;
    const size_t NK = (size_t)KVDIM * DIM;
    const size_t NX = (size_t)M_TOK * DIM;
    size_t i = ((size_t)blockIdx.x * blockDim.x + threadIdx.x) * 16;
    const float* src; __half* dst; size_t off;
    if      (i < NW)                    { src = wq; dst = owq; off = i; }
    else if (i < NW + NK)               { src = wk; dst = owk; off = i - NW; }
    else if (i < NW + 2 * NK)           { src = wv; dst = owv; off = i - NW - NK; }
    else if (i < 2 * NW + 2 * NK)       { src = wo; dst = owo; off = i - NW - 2 * NK; }
    else if (i < 2 * NW + 2 * NK + NX)  { src = x;  dst = ox;  off = i - 2 * NW - 2 * NK; }
    else return;
    float4 v0 = *(const float4*)&src[off];
    float4 v1 = *(const float4*)&src[off + 4];
    float4 v2 = *(const float4*)&src[off + 8];
    float4 v3 = *(const float4*)&src[off + 12];
    *(__half2*)&dst[off]      = __floats2half2_rn(v0.x, v0.y);
    *(__half2*)&dst[off + 2]  = __floats2half2_rn(v0.z, v0.w);
    *(__half2*)&dst[off + 4]  = __floats2half2_rn(v1.x, v1.y);
    *(__half2*)&dst[off + 6]  = __floats2half2_rn(v1.z, v1.w);
    *(__half2*)&dst[off + 8]  = __floats2half2_rn(v2.x, v2.y);
    *(__half2*)&dst[off + 10] = __floats2half2_rn(v2.z, v2.w);
    *(__half2*)&dst[off + 12] = __floats2half2_rn(v3.x, v3.y);
    *(__half2*)&dst[off + 14] = __floats2half2_rn(v3.z, v3.w);
}

// ---------------------------------------------------------------------------
// common PTX helpers
// ---------------------------------------------------------------------------
__device__ __forceinline__ void cpasync16(const void* s, const void* g) {
    u32 sa = (u32)__cvta_generic_to_shared(s);
    asm volatile("cp.async.cg.shared.global [%0], [%1], 16;\n" :: "r"(sa), "l"(g));
}
__device__ __forceinline__ void ldsm4(u32& r0, u32& r1, u32& r2,
                                      u32& r3, const void* p) {
    u32 a = (u32)__cvta_generic_to_shared(p);
    asm volatile("ldmatrix.sync.aligned.m8n8.x4.shared.b16 {%0,%1,%2,%3}, [%4];"
                 : "=r"(r0), "=r"(r1), "=r"(r2), "=r"(r3) : "r"(a));
}
__device__ __forceinline__ void ldsm4t(u32& r0, u32& r1, u32& r2,
                                       u32& r3, const void* p) {
    u32 a = (u32)__cvta_generic_to_shared(p);
    asm volatile("ldmatrix.sync.aligned.m8n8.x4.trans.shared.b16 {%0,%1,%2,%3}, [%4];"
                 : "=r"(r0), "=r"(r1), "=r"(r2), "=r"(r3) : "r"(a));
}
__device__ __forceinline__ void mma16816h(float* c, const u32* a, const u32* b) {
    asm volatile(
        "mma.sync.aligned.m16n8k16.row.col.f32.f16.f16.f32 "
        "{%0,%1,%2,%3}, {%4,%5,%6,%7}, {%8,%9}, {%0,%1,%2,%3};"
        : "+f"(c[0]), "+f"(c[1]), "+f"(c[2]), "+f"(c[3])
        : "r"(a[0]), "r"(a[1]), "r"(a[2]), "r"(a[3]), "r"(b[0]), "r"(b[1]));
}
__device__ __forceinline__ u32 pack_h2(float a, float b) {
    __half2 h = __floats2half2_rn(a, b);
    return *(u32*)&h;
}

// ---------------------------------------------------------------------------
// GEMM mainloop: 128x128 tile, BK=64, 256 threads = 8 warps (2x4),
// warp tile 64x32, 2-stage cp.async with loads interleaved into the kk loop.
// ---------------------------------------------------------------------------
#define KSTR 72
#define KTILE (128*KSTR)
#define GEMM_SMEM (2 * 2 * KTILE * 2)    // 73728 bytes

// issue 1/4 of a stage: 2 cp.async per thread (chunk = 0..3)
__device__ __forceinline__ void load_chunk(
    __half* sb, const __half* __restrict__ A, const __half* __restrict__ Bm,
    int tid, int m0, int n0, int K, int k0, int chunk)
{
    int c = tid + chunk * 256;           // 0..1023
    int row = c >> 3;
    int ch  = (c & 7) * 8;
    cpasync16(&sb[row * KSTR + ch],         &A[(size_t)(m0 + row) * K + k0 + ch]);
    cpasync16(&sb[KTILE + row * KSTR + ch], &Bm[(size_t)(n0 + row) * K + k0 + ch]);
}

__device__ __forceinline__ void gemm_mainloop(
    __half* smem, float acc[4][4][4],
    const __half* __restrict__ A, const __half* __restrict__ Bm,
    int tid, int lane, int wm, int wn, int m0, int n0, int K)
{
    const int KT = K / 64;
#pragma unroll
    for (int ck = 0; ck < 4; ck++)
        load_chunk(smem, A, Bm, tid, m0, n0, K, 0, ck);
    asm volatile("cp.async.commit_group;");
    asm volatile("cp.async.wait_group 0;");
    __syncthreads();

    for (int kt = 0; kt < KT; kt++) {
        int cur = kt & 1;
        bool more = (kt + 1 < KT);
        __half* nb = smem + (cur ^ 1) * 2 * KTILE;
        int nk0 = (kt + 1) * 64;

#pragma unroll
        for (int kk = 0; kk < 64; kk += 16) {
            // interleave: one quarter of the next-stage load per kk-step
            if (more) load_chunk(nb, A, Bm, tid, m0, n0, K, nk0, kk >> 4);

            const __half* sA = smem + cur * 2 * KTILE;
            const __half* sB = sA + KTILE;
            u32 ah[4][4], bb[4][2];
            int arow = wm * 64 + (lane & 7) + ((lane >> 3) & 1) * 8;
            int acol = kk + ((lane >> 4) & 1) * 8;
#pragma unroll
            for (int mt = 0; mt < 4; mt++)
                ldsm4(ah[mt][0], ah[mt][1], ah[mt][2], ah[mt][3],
                      sA + (arow + mt * 16) * KSTR + acol);
            int brow = wn * 32 + (lane & 7) + ((lane >> 4) & 1) * 8;
            int bcol = kk + ((lane >> 3) & 1) * 8;
#pragma unroll
            for (int p = 0; p < 2; p++) {
                u32 r0, r1, r2, r3;
                ldsm4(r0, r1, r2, r3, sB + (brow + p * 16) * KSTR + bcol);
                bb[2 * p][0] = r0; bb[2 * p][1] = r1;
                bb[2 * p + 1][0] = r2; bb[2 * p + 1][1] = r3;
            }
#pragma unroll
            for (int mt = 0; mt < 4; mt++)
#pragma unroll
                for (int nt = 0; nt < 4; nt++)
                    mma16816h(acc[mt][nt], ah[mt], bb[nt]);
        }
        asm volatile("cp.async.commit_group;");
        asm volatile("cp.async.wait_group 0;");
        __syncthreads();
    }
}

// ---------------------------------------------------------------------------
// fused QKV GEMM (single-pass fp16) + RoPE epilogue. grid: (48, M/128), 256 thr
// ---------------------------------------------------------------------------
__global__ __launch_bounds__(256, 2) void gemm_qkv(
    const __half* __restrict__ A,
    const __half* __restrict__ Wq, const __half* __restrict__ Wk,
    const __half* __restrict__ Wv,
    __half* __restrict__ qh, __half* __restrict__ kh, __half* __restrict__ vh,
    const float* __restrict__ fc, const float* __restrict__ fs)
{
    extern __shared__ __half smem[];
    int tid = threadIdx.x;
    int lane = tid & 31, wid = tid >> 5;
    int wm = wid & 1, wn = wid >> 1;
    int m0 = blockIdx.y * 128;

    int bx = blockIdx.x;
    int seg = (bx < 32) ? 0 : ((bx < 40) ? 1 : 2);
    int bn0 = (seg == 0) ? bx * 128 : ((seg == 1) ? (bx - 32) * 128 : (bx - 40) * 128);
    const __half* Bm = (seg == 0) ? Wq : ((seg == 1) ? Wk : Wv);
    int Nout = (seg == 0) ? DIM : KVDIM;

    float acc[4][4][4];
#pragma unroll
    for (int i = 0; i < 4; i++)
#pragma unroll
        for (int j = 0; j < 4; j++)
#pragma unroll
            for (int k = 0; k < 4; k++) acc[i][j][k] = 0.f;

    gemm_mainloop(smem, acc, A, Bm, tid, lane, wm, wn, m0, bn0, DIM);

    const float scale = 0.08838834764831845f;

#pragma unroll
    for (int mt = 0; mt < 4; mt++) {
#pragma unroll
        for (int nt = 0; nt < 4; nt++) {
            int r  = m0 + wm * 64 + mt * 16 + (lane >> 2);
            int cl = bn0 + wn * 32 + nt * 8 + (lane & 3) * 2;
            float a0 = acc[mt][nt][0], a1 = acc[mt][nt][1];
            float a2 = acc[mt][nt][2], a3 = acc[mt][nt][3];
            size_t o0 = (size_t)r * Nout + cl;
            size_t o1 = (size_t)(r + 8) * Nout + cl;

            if (seg == 2) {
                *(u32*)&vh[o0] = pack_h2(a0, a1);
                *(u32*)&vh[o1] = pack_h2(a2, a3);
            } else {
                int p  = (cl & 127) >> 1;
                int s0 = r & (SS - 1), s1 = (r + 8) & (SS - 1);
                float c0f = fc[s0 * 64 + p], sn0 = fs[s0 * 64 + p];
                float c1f = fc[s1 * 64 + p], sn1 = fs[s1 * 64 + p];
                float r0 = a0 * c0f - a1 * sn0, i0 = a0 * sn0 + a1 * c0f;
                float r1 = a2 * c1f - a3 * sn1, i1 = a2 * sn1 + a3 * c1f;
                if (seg == 0) {
                    r0 *= scale; i0 *= scale; r1 *= scale; i1 *= scale;
                    *(u32*)&qh[o0] = pack_h2(r0, i0);
                    *(u32*)&qh[o1] = pack_h2(r1, i1);
                } else {
                    *(u32*)&kh[o0] = pack_h2(r0, i0);
                    *(u32*)&kh[o1] = pack_h2(r1, i1);
                }
            }
        }
    }
}

// ---------------------------------------------------------------------------
// wo GEMM (single-pass fp16 A), fp32 out.
// ---------------------------------------------------------------------------
__global__ __launch_bounds__(256, 2) void gemm_wo(
    const __half* __restrict__ A, const __half* __restrict__ Bm,
    float* __restrict__ C, int N, int K)
{
    extern __shared__ __half smem[];
    int tid = threadIdx.x;
    int lane = tid & 31, wid = tid >> 5;
    int wm = wid & 1, wn = wid >> 1;
    int m0 = blockIdx.y * 128, n0 = blockIdx.x * 128;

    float acc[4][4][4];
#pragma unroll
    for (int i = 0; i < 4; i++)
#pragma unroll
        for (int j = 0; j < 4; j++)
#pragma unroll
            for (int k = 0; k < 4; k++) acc[i][j][k] = 0.f;

    gemm_mainloop(smem, acc, A, Bm, tid, lane, wm, wn, m0, n0, K);

#pragma unroll
    for (int mt = 0; mt < 4; mt++) {
#pragma unroll
        for (int nt = 0; nt < 4; nt++) {
            int r = m0 + wm * 64 + mt * 16 + (lane >> 2);
            int c = n0 + wn * 32 + nt * 8 + (lane & 3) * 2;
            *(float2*)&C[(size_t)r * N + c] =
                make_float2(acc[mt][nt][0], acc[mt][nt][1]);
            *(float2*)&C[(size_t)(r + 8) * N + c] =
                make_float2(acc[mt][nt][2], acc[mt][nt][3]);
        }
    }
}

// ---------------------------------------------------------------------------
// fast exp on the FMA pipe
// ---------------------------------------------------------------------------
__device__ __forceinline__ float fast_exp(float x) {
    x = fmaxf(x, -87.f);
    float z = x * 1.4426950408889634f;
    float t = z + 12582912.f;
    int   e = __float_as_int(t) << 23;
    float n = t - 12582912.f;
    float f = z - n;
    float p = 1.3387706e-3f;
    p = fmaf(p, f, 9.6181291e-3f);
    p = fmaf(p, f, 5.5504108e-2f);
    p = fmaf(p, f, 2.4022650e-1f);
    p = fmaf(p, f, 6.9314718e-1f);
    p = fmaf(p, f, 1.0f);
    return __int_as_float(__float_as_int(p) + e);
}

// ---------------------------------------------------------------------------
// Tensor-core flash attention (round-14 verbatim): single-pass S, fp16 P@V,
// fp16 out. BM=BN=64, 4 warps. smem 52224 B.
// ---------------------------------------------------------------------------
#define FSTR 136
#define FA2_TILE (64 * FSTR)
#define FA2_SMEM (3 * FA2_TILE * 2)   // 52224 B

__global__ __launch_bounds__(128) void flash_mma(
    const __half* __restrict__ qh, const __half* __restrict__ kh,
    const __half* __restrict__ vv, __half* __restrict__ outh)
{
    extern __shared__ __half sm2[];
    __half* sqh = sm2;
    __half* skh = sqh + FA2_TILE;
    __half* sv  = skh + FA2_TILE;

    int tid = threadIdx.x, lane = tid & 31, wid = tid >> 5;
    int qt = gridDim.x - 1 - blockIdx.x;
    int bh = blockIdx.y;
    int b = bh >> 5, h = bh & 31, kvh = h >> 2;
    int q0 = qt * 64;

#pragma unroll
    for (int i = 0; i < 8; i++) {
        int c = tid + i * 128;
        int row = c >> 4;
        int col = (c & 15) * 8;
        size_t g = ((size_t)(b * SS + q0 + row) * NH + h) * HD + col;
        *(int4*)&sqh[row * FSTR + col] = *(const int4*)&qh[g];
    }

    float o[16][4];
#pragma unroll
    for (int n = 0; n < 16; n++)
#pragma unroll
        for (int j = 0; j < 4; j++) o[n][j] = 0.f;
    float m0 = -1e30f, m1 = -1e30f, l0 = 0.f, l1 = 0.f;

    int gr = lane >> 2, qc = (lane & 3) * 2;
    int arow = wid * 16 + (lane & 7) + ((lane >> 3) & 1) * 8;
    int acolo = ((lane >> 4) & 1) * 8;
    int brow = (lane & 7) + ((lane >> 4) & 1) * 8;
    int bcolo = ((lane >> 3) & 1) * 8;
    int vrow = (lane & 7) + ((lane >> 3) & 1) * 8;
    int vcolo = ((lane >> 4) & 1) * 8;

    for (int nt = 0; nt <= qt; nt++) {
        int k0 = nt * 64;
        __syncthreads();
#pragma unroll
        for (int i = 0; i < 8; i++) {
            int c = tid + i * 128;
            int row = c >> 4;
            int col = (c & 15) * 8;
            size_t g = ((size_t)(b * SS + k0 + row) * NKV + kvh) * HD + col;
            *(int4*)&skh[row * FSTR + col] = *(const int4*)&kh[g];
            *(int4*)&sv [row * FSTR + col] = *(const int4*)&vv[g];
        }
        __syncthreads();

        float s[8][4];
#pragma unroll
        for (int n = 0; n < 8; n++)
#pragma unroll
            for (int j = 0; j < 4; j++) s[n][j] = 0.f;

#pragma unroll
        for (int kc = 0; kc < 8; kc++) {
            u32 aH[4];
            ldsm4(aH[0], aH[1], aH[2], aH[3], &sqh[arow * FSTR + kc * 16 + acolo]);
            u32 bH[8][2];
#pragma unroll
            for (int p = 0; p < 4; p++) {
                u32 r0, r1, r2, r3;
                ldsm4(r0, r1, r2, r3, &skh[(p * 16 + brow) * FSTR + kc * 16 + bcolo]);
                bH[2 * p][0] = r0; bH[2 * p][1] = r1;
                bH[2 * p + 1][0] = r2; bH[2 * p + 1][1] = r3;
            }
#pragma unroll
            for (int n = 0; n < 8; n++) mma16816h(s[n], aH, bH[n]);
        }

        if (nt == qt) {
            int lr0 = wid * 16 + gr, lr1 = lr0 + 8;
#pragma unroll
            for (int n = 0; n < 8; n++) {
                int lc = n * 8 + qc;
                if (lc     > lr0) s[n][0] = -1e30f;
                if (lc + 1 > lr0) s[n][1] = -1e30f;
                if (lc     > lr1) s[n][2] = -1e30f;
                if (lc + 1 > lr1) s[n][3] = -1e30f;
            }
        }

        float mx0 = -1e30f, mx1 = -1e30f;
#pragma unroll
        for (int n = 0; n < 8; n++) {
            mx0 = fmaxf(mx0, fmaxf(s[n][0], s[n][1]));
            mx1 = fmaxf(mx1, fmaxf(s[n][2], s[n][3]));
        }
        mx0 = fmaxf(mx0, __shfl_xor_sync(0xffffffffu, mx0, 1));
        mx0 = fmaxf(mx0, __shfl_xor_sync(0xffffffffu, mx0, 2));
        mx1 = fmaxf(mx1, __shfl_xor_sync(0xffffffffu, mx1, 1));
        mx1 = fmaxf(mx1, __shfl_xor_sync(0xffffffffu, mx1, 2));
        float nm0 = fmaxf(m0, mx0), nm1 = fmaxf(m1, mx1);
        float a0 = fast_exp(m0 - nm0), a1 = fast_exp(m1 - nm1);
        m0 = nm0; m1 = nm1;

        float ls0 = 0.f, ls1 = 0.f;
        u32 pa[4][4];
#pragma unroll
        for (int n = 0; n < 8; n++) {
            float p0 = fast_exp(s[n][0] - nm0);
            float p1 = fast_exp(s[n][1] - nm0);
            float p2 = fast_exp(s[n][2] - nm1);
            float p3 = fast_exp(s[n][3] - nm1);
            ls0 += p0 + p1; ls1 += p2 + p3;
            __half2 hi = __floats2half2_rn(p0, p1);
            __half2 lo = __floats2half2_rn(p2, p3);
            int j = n >> 1;
            if ((n & 1) == 0) {
                pa[j][0] = *(u32*)&hi; pa[j][1] = *(u32*)&lo;
            } else {
                pa[j][2] = *(u32*)&hi; pa[j][3] = *(u32*)&lo;
            }
        }
        ls0 += __shfl_xor_sync(0xffffffffu, ls0, 1);
        ls0 += __shfl_xor_sync(0xffffffffu, ls0, 2);
        ls1 += __shfl_xor_sync(0xffffffffu, ls1, 1);
        ls1 += __shfl_xor_sync(0xffffffffu, ls1, 2);
        l0 = l0 * a0 + ls0;
        l1 = l1 * a1 + ls1;

#pragma unroll
        for (int n = 0; n < 16; n++) {
            o[n][0] *= a0; o[n][1] *= a0;
            o[n][2] *= a1; o[n][3] *= a1;
        }

#pragma unroll
        for (int np = 0; np < 8; np++) {
#pragma unroll
            for (int j = 0; j < 4; j++) {
                u32 r0, r1, r2, r3;
                ldsm4t(r0, r1, r2, r3, &sv[(j * 16 + vrow) * FSTR + np * 16 + vcolo]);
                u32 bv0[2] = {r0, r1};
                u32 bv1[2] = {r2, r3};
                mma16816h(o[2 * np],     pa[j], bv0);
                mma16816h(o[2 * np + 1], pa[j], bv1);
            }
        }
    }

    float inv0 = 1.f / l0, inv1 = 1.f / l1;
    int row0 = q0 + wid * 16 + gr;
#pragma unroll
    for (int n = 0; n < 16; n++) {
        int col = n * 8 + qc;
        size_t base0 = ((size_t)(b * SS + row0)     * NH + h) * HD + col;
        size_t base1 = ((size_t)(b * SS + row0 + 8) * NH + h) * HD + col;
        *(u32*)&outh[base0] = pack_h2(o[n][0] * inv0, o[n][1] * inv0);
        *(u32*)&outh[base1] = pack_h2(o[n][2] * inv1, o[n][3] * inv1);
    }
}

// ---------------------------------------------------------------------------
extern "C" void kernel_launch(void* const* d_in, const int* in_sizes, int n_in,
                              void* d_out, int out_size)
{
    const float* x   = (const float*)d_in[0];
    const float* wq  = (const float*)d_in[1];
    const float* wk  = (const float*)d_in[2];
    const float* wv  = (const float*)d_in[3];
    const float* wo  = (const float*)d_in[4];
    const float* fc  = (const float*)d_in[5];
    const float* fs  = (const float*)d_in[6];
    float* out = (float*)d_out;

    __half *xh, *wqf, *wkf, *wvf, *wof;
    cudaGetSymbolAddress((void**)&xh, g_xh);
    cudaGetSymbolAddress((void**)&wqf, g_wq);  cudaGetSymbolAddress((void**)&wkf, g_wk);
    cudaGetSymbolAddress((void**)&wvf, g_wv);  cudaGetSymbolAddress((void**)&wof, g_wo);
    __half *qhp, *khp, *vhp, *ahp;
    cudaGetSymbolAddress((void**)&qhp, g_qh);  cudaGetSymbolAddress((void**)&khp, g_kh);
    cudaGetSymbolAddress((void**)&vhp, g_vh);  cudaGetSymbolAddress((void**)&ahp, g_ah);

    cudaFuncSetAttribute(gemm_qkv, cudaFuncAttributeMaxDynamicSharedMemorySize, GEMM_SMEM);
    cudaFuncSetAttribute(gemm_wo, cudaFuncAttributeMaxDynamicSharedMemorySize, GEMM_SMEM);
    cudaFuncSetAttribute(flash_mma, cudaFuncAttributeMaxDynamicSharedMemorySize, FA2_SMEM);

    // prep: all weights + x -> fp16
    size_t total = 2 * (size_t)DIM * DIM + 2 * (size_t)KVDIM * DIM + (size_t)M_TOK * DIM;
    prep_half<<<(unsigned)(total / 16 / 256), 256>>>(wq, wk, wv, wo, x,
                                                     wqf, wkf, wvf, wof, xh);

    // fused QKV projection + RoPE (q, k, v all fp16)
    dim3 gqkv(48, M_TOK / 128);
    gemm_qkv<<<gqkv, 256, GEMM_SMEM>>>(xh, wqf, wkf, wvf, qhp, khp, vhp, fc, fs);

    // attention (single-pass S, BM=64, fp16 out)
    dim3 ga(SS / 64, BB * NH);
    flash_mma<<<ga, 128, FA2_SMEM>>>(qhp, khp, vhp, ahp);

    // output projection
    dim3 gq(DIM / 128, M_TOK / 128);
    gemm_wo<<<gq, 256, GEMM_SMEM>>>(ahp, wof, out, DIM, DIM);
}

// round 17
// speedup vs baseline: 1.0410x; 1.0039x over previous
#include <cuda_runtime.h>
#include <cuda_fp16.h>
#include <cstdint>
#include <cstddef>
#include <math.h>
#include <float.h>

typedef unsigned int u32;

#define BB 2
#define SS 2048
#define DIM 4096
#define NH 32
#define NKV 8
#define HD 128
#define NREP 4
#define M_TOK (BB*SS)
#define KVDIM (NKV*HD)

// ---------------- scratch (allocation-free device globals) ----------------
__device__ __half g_xh[(size_t)M_TOK * DIM];
__device__ __half g_wq[(size_t)DIM * DIM],    g_wo[(size_t)DIM * DIM];
__device__ __half g_wk[(size_t)KVDIM * DIM],  g_wv[(size_t)KVDIM * DIM];
__device__ __half g_qh[(size_t)M_TOK * DIM];
__device__ __half g_kh[(size_t)M_TOK * KVDIM];
__device__ __half g_vh[(size_t)M_TOK * KVDIM];
__device__ __half g_ah[(size_t)M_TOK * DIM];

// ---------------------------------------------------------------------------
// prep: fp32 -> fp16, 4 independent float4 per thread (MLP=4)
// ---------------------------------------------------------------------------
__global__ void prep_half(const float* __restrict__ wq, const float* __restrict__ wk,
                          const float* __restrict__ wv, const float* __restrict__ wo,
                          const float* __restrict__ x,
                          __half* __restrict__ owq, __half* __restrict__ owk,
                          __half* __restrict__ owv, __half* __restrict__ owo,
                          __half* __restrict__ ox)
{
    const size_t NW = (size_t)DIM * DIM;
    const size_t NK = (size_t)KVDIM * DIM;
    const size_t NX = (size_t)M_TOK * DIM;
    size_t i = ((size_t)blockIdx.x * blockDim.x + threadIdx.x) * 16;
    const float* src; __half* dst; size_t off;
    if      (i < NW)                    { src = wq; dst = owq; off = i; }
    else if (i < NW + NK)               { src = wk; dst = owk; off = i - NW; }
    else if (i < NW + 2 * NK)           { src = wv; dst = owv; off = i - NW - NK; }
    else if (i < 2 * NW + 2 * NK)       { src = wo; dst = owo; off = i - NW - 2 * NK; }
    else if (i < 2 * NW + 2 * NK + NX)  { src = x;  dst = ox;  off = i - 2 * NW - 2 * NK; }
    else return;
    float4 v0 = *(const float4*)&src[off];
    float4 v1 = *(const float4*)&src[off + 4];
    float4 v2 = *(const float4*)&src[off + 8];
    float4 v3 = *(const float4*)&src[off + 12];
    *(__half2*)&dst[off]      = __floats2half2_rn(v0.x, v0.y);
    *(__half2*)&dst[off + 2]  = __floats2half2_rn(v0.z, v0.w);
    *(__half2*)&dst[off + 4]  = __floats2half2_rn(v1.x, v1.y);
    *(__half2*)&dst[off + 6]  = __floats2half2_rn(v1.z, v1.w);
    *(__half2*)&dst[off + 8]  = __floats2half2_rn(v2.x, v2.y);
    *(__half2*)&dst[off + 10] = __floats2half2_rn(v2.z, v2.w);
    *(__half2*)&dst[off + 12] = __floats2half2_rn(v3.x, v3.y);
    *(__half2*)&dst[off + 14] = __floats2half2_rn(v3.z, v3.w);
}

// ---------------------------------------------------------------------------
// common PTX helpers
// ---------------------------------------------------------------------------
__device__ __forceinline__ void cpasync16(const void* s, const void* g) {
    u32 sa = (u32)__cvta_generic_to_shared(s);
    asm volatile("cp.async.cg.shared.global [%0], [%1], 16;\n" :: "r"(sa), "l"(g));
}
__device__ __forceinline__ void ldsm4(u32& r0, u32& r1, u32& r2,
                                      u32& r3, const void* p) {
    u32 a = (u32)__cvta_generic_to_shared(p);
    asm volatile("ldmatrix.sync.aligned.m8n8.x4.shared.b16 {%0,%1,%2,%3}, [%4];"
                 : "=r"(r0), "=r"(r1), "=r"(r2), "=r"(r3) : "r"(a));
}
__device__ __forceinline__ void ldsm4t(u32& r0, u32& r1, u32& r2,
                                       u32& r3, const void* p) {
    u32 a = (u32)__cvta_generic_to_shared(p);
    asm volatile("ldmatrix.sync.aligned.m8n8.x4.trans.shared.b16 {%0,%1,%2,%3}, [%4];"
                 : "=r"(r0), "=r"(r1), "=r"(r2), "=r"(r3) : "r"(a));
}
__device__ __forceinline__ void mma16816h(float* c, const u32* a, const u32* b) {
    asm volatile(
        "mma.sync.aligned.m16n8k16.row.col.f32.f16.f16.f32 "
        "{%0,%1,%2,%3}, {%4,%5,%6,%7}, {%8,%9}, {%0,%1,%2,%3};"
        : "+f"(c[0]), "+f"(c[1]), "+f"(c[2]), "+f"(c[3])
        : "r"(a[0]), "r"(a[1]), "r"(a[2]), "r"(a[3]), "r"(b[0]), "r"(b[1]));
}
__device__ __forceinline__ u32 pack_h2(float a, float b) {
    __half2 h = __floats2half2_rn(a, b);
    return *(u32*)&h;
}

// ---------------------------------------------------------------------------
// GEMM tiles: 128x128, BK=64, 256 threads = 8 warps (2x4), warp tile 64x32.
// ---------------------------------------------------------------------------
#define KSTR 72
#define KTILE (128*KSTR)
#define GEMM_SMEM (2 * 2 * KTILE * 2)    // 73728 bytes

// 1/4 of a stage: 2 cp.async per thread
__device__ __forceinline__ void load_chunk(
    __half* sb, const __half* __restrict__ A, const __half* __restrict__ Bm,
    int tid, int m0, int n0, int K, int k0, int chunk)
{
    int c = tid + chunk * 256;
    int row = c >> 3;
    int ch  = (c & 7) * 8;
    cpasync16(&sb[row * KSTR + ch],         &A[(size_t)(m0 + row) * K + k0 + ch]);
    cpasync16(&sb[KTILE + row * KSTR + ch], &Bm[(size_t)(n0 + row) * K + k0 + ch]);
}

// shared compute for one kk step
__device__ __forceinline__ void kk_step(
    const __half* sA, const __half* sB, float acc[4][4][4],
    int lane, int wm, int wn, int kk)
{
    u32 ah[4][4], bb[4][2];
    int arow = wm * 64 + (lane & 7) + ((lane >> 3) & 1) * 8;
    int acol = kk + ((lane >> 4) & 1) * 8;
#pragma unroll
    for (int mt = 0; mt < 4; mt++)
        ldsm4(ah[mt][0], ah[mt][1], ah[mt][2], ah[mt][3],
              sA + (arow + mt * 16) * KSTR + acol);
    int brow = wn * 32 + (lane & 7) + ((lane >> 4) & 1) * 8;
    int bcol = kk + ((lane >> 3) & 1) * 8;
#pragma unroll
    for (int p = 0; p < 2; p++) {
        u32 r0, r1, r2, r3;
        ldsm4(r0, r1, r2, r3, sB + (brow + p * 16) * KSTR + bcol);
        bb[2 * p][0] = r0; bb[2 * p][1] = r1;
        bb[2 * p + 1][0] = r2; bb[2 * p + 1][1] = r3;
    }
#pragma unroll
    for (int mt = 0; mt < 4; mt++)
#pragma unroll
        for (int nt = 0; nt < 4; nt++)
            mma16816h(acc[mt][nt], ah[mt], bb[nt]);
}

// variant A (round-16): next-stage loads interleaved into the kk loop
__device__ __forceinline__ void mainloop_ilv(
    __half* smem, float acc[4][4][4],
    const __half* __restrict__ A, const __half* __restrict__ Bm,
    int tid, int lane, int wm, int wn, int m0, int n0, int K)
{
    const int KT = K / 64;
#pragma unroll
    for (int ck = 0; ck < 4; ck++)
        load_chunk(smem, A, Bm, tid, m0, n0, K, 0, ck);
    asm volatile("cp.async.commit_group;");
    asm volatile("cp.async.wait_group 0;");
    __syncthreads();

    for (int kt = 0; kt < KT; kt++) {
        int cur = kt & 1;
        bool more = (kt + 1 < KT);
        __half* nb = smem + (cur ^ 1) * 2 * KTILE;
        int nk0 = (kt + 1) * 64;
        const __half* sA = smem + cur * 2 * KTILE;
        const __half* sB = sA + KTILE;
#pragma unroll
        for (int kk = 0; kk < 64; kk += 16) {
            if (more) load_chunk(nb, A, Bm, tid, m0, n0, K, nk0, kk >> 4);
            kk_step(sA, sB, acc, lane, wm, wn, kk);
        }
        asm volatile("cp.async.commit_group;");
        asm volatile("cp.async.wait_group 0;");
        __syncthreads();
    }
}

// variant B (round-14): bursty loads at the loop head
__device__ __forceinline__ void mainloop_burst(
    __half* smem, float acc[4][4][4],
    const __half* __restrict__ A, const __half* __restrict__ Bm,
    int tid, int lane, int wm, int wn, int m0, int n0, int K)
{
    const int KT = K / 64;
#pragma unroll
    for (int ck = 0; ck < 4; ck++)
        load_chunk(smem, A, Bm, tid, m0, n0, K, 0, ck);
    asm volatile("cp.async.commit_group;");
    asm volatile("cp.async.wait_group 0;");
    __syncthreads();

    for (int kt = 0; kt < KT; kt++) {
        int cur = kt & 1;
        if (kt + 1 < KT) {
            __half* nb = smem + (cur ^ 1) * 2 * KTILE;
#pragma unroll
            for (int ck = 0; ck < 4; ck++)
                load_chunk(nb, A, Bm, tid, m0, n0, K, (kt + 1) * 64, ck);
            asm volatile("cp.async.commit_group;");
        }
        const __half* sA = smem + cur * 2 * KTILE;
        const __half* sB = sA + KTILE;
#pragma unroll
        for (int kk = 0; kk < 64; kk += 16)
            kk_step(sA, sB, acc, lane, wm, wn, kk);
        asm volatile("cp.async.wait_group 0;");
        __syncthreads();
    }
}

// ---------------------------------------------------------------------------
// fused QKV GEMM (single-pass fp16, interleaved loader) + RoPE epilogue.
// ---------------------------------------------------------------------------
__global__ __launch_bounds__(256, 2) void gemm_qkv(
    const __half* __restrict__ A,
    const __half* __restrict__ Wq, const __half* __restrict__ Wk,
    const __half* __restrict__ Wv,
    __half* __restrict__ qh, __half* __restrict__ kh, __half* __restrict__ vh,
    const float* __restrict__ fc, const float* __restrict__ fs)
{
    extern __shared__ __half smem[];
    int tid = threadIdx.x;
    int lane = tid & 31, wid = tid >> 5;
    int wm = wid & 1, wn = wid >> 1;
    int m0 = blockIdx.y * 128;

    int bx = blockIdx.x;
    int seg = (bx < 32) ? 0 : ((bx < 40) ? 1 : 2);
    int bn0 = (seg == 0) ? bx * 128 : ((seg == 1) ? (bx - 32) * 128 : (bx - 40) * 128);
    const __half* Bm = (seg == 0) ? Wq : ((seg == 1) ? Wk : Wv);
    int Nout = (seg == 0) ? DIM : KVDIM;

    float acc[4][4][4];
#pragma unroll
    for (int i = 0; i < 4; i++)
#pragma unroll
        for (int j = 0; j < 4; j++)
#pragma unroll
            for (int k = 0; k < 4; k++) acc[i][j][k] = 0.f;

    mainloop_ilv(smem, acc, A, Bm, tid, lane, wm, wn, m0, bn0, DIM);

    const float scale = 0.08838834764831845f;

#pragma unroll
    for (int mt = 0; mt < 4; mt++) {
#pragma unroll
        for (int nt = 0; nt < 4; nt++) {
            int r  = m0 + wm * 64 + mt * 16 + (lane >> 2);
            int cl = bn0 + wn * 32 + nt * 8 + (lane & 3) * 2;
            float a0 = acc[mt][nt][0], a1 = acc[mt][nt][1];
            float a2 = acc[mt][nt][2], a3 = acc[mt][nt][3];
            size_t o0 = (size_t)r * Nout + cl;
            size_t o1 = (size_t)(r + 8) * Nout + cl;

            if (seg == 2) {
                *(u32*)&vh[o0] = pack_h2(a0, a1);
                *(u32*)&vh[o1] = pack_h2(a2, a3);
            } else {
                int p  = (cl & 127) >> 1;
                int s0 = r & (SS - 1), s1 = (r + 8) & (SS - 1);
                float c0f = fc[s0 * 64 + p], sn0 = fs[s0 * 64 + p];
                float c1f = fc[s1 * 64 + p], sn1 = fs[s1 * 64 + p];
                float r0 = a0 * c0f - a1 * sn0, i0 = a0 * sn0 + a1 * c0f;
                float r1 = a2 * c1f - a3 * sn1, i1 = a2 * sn1 + a3 * c1f;
                if (seg == 0) {
                    r0 *= scale; i0 *= scale; r1 *= scale; i1 *= scale;
                    *(u32*)&qh[o0] = pack_h2(r0, i0);
                    *(u32*)&qh[o1] = pack_h2(r1, i1);
                } else {
                    *(u32*)&kh[o0] = pack_h2(r0, i0);
                    *(u32*)&kh[o1] = pack_h2(r1, i1);
                }
            }
        }
    }
}

// ---------------------------------------------------------------------------
// wo GEMM (single-pass fp16 A, bursty loader), fp32 out.
// ---------------------------------------------------------------------------
__global__ __launch_bounds__(256, 2) void gemm_wo(
    const __half* __restrict__ A, const __half* __restrict__ Bm,
    float* __restrict__ C, int N, int K)
{
    extern __shared__ __half smem[];
    int tid = threadIdx.x;
    int lane = tid & 31, wid = tid >> 5;
    int wm = wid & 1, wn = wid >> 1;
    int m0 = blockIdx.y * 128, n0 = blockIdx.x * 128;

    float acc[4][4][4];
#pragma unroll
    for (int i = 0; i < 4; i++)
#pragma unroll
        for (int j = 0; j < 4; j++)
#pragma unroll
            for (int k = 0; k < 4; k++) acc[i][j][k] = 0.f;

    mainloop_burst(smem, acc, A, Bm, tid, lane, wm, wn, m0, n0, K);

#pragma unroll
    for (int mt = 0; mt < 4; mt++) {
#pragma unroll
        for (int nt = 0; nt < 4; nt++) {
            int r = m0 + wm * 64 + mt * 16 + (lane >> 2);
            int c = n0 + wn * 32 + nt * 8 + (lane & 3) * 2;
            *(float2*)&C[(size_t)r * N + c] =
                make_float2(acc[mt][nt][0], acc[mt][nt][1]);
            *(float2*)&C[(size_t)(r + 8) * N + c] =
                make_float2(acc[mt][nt][2], acc[mt][nt][3]);
        }
    }
}

// ---------------------------------------------------------------------------
// fast exp on the FMA pipe
// ---------------------------------------------------------------------------
__device__ __forceinline__ float fast_exp(float x) {
    x = fmaxf(x, -87.f);
    float z = x * 1.4426950408889634f;
    float t = z + 12582912.f;
    int   e = __float_as_int(t) << 23;
    float n = t - 12582912.f;
    float f = z - n;
    float p = 1.3387706e-3f;
    p = fmaf(p, f, 9.6181291e-3f);
    p = fmaf(p, f, 5.5504108e-2f);
    p = fmaf(p, f, 2.4022650e-1f);
    p = fmaf(p, f, 6.9314718e-1f);
    p = fmaf(p, f, 1.0f);
    return __int_as_float(__float_as_int(p) + e);
}

// ---------------------------------------------------------------------------
// Tensor-core flash attention (round-14 verbatim): single-pass S, fp16 P@V,
// fp16 out. BM=BN=64, 4 warps. smem 52224 B.
// ---------------------------------------------------------------------------
#define FSTR 136
#define FA2_TILE (64 * FSTR)
#define FA2_SMEM (3 * FA2_TILE * 2)   // 52224 B

__global__ __launch_bounds__(128) void flash_mma(
    const __half* __restrict__ qh, const __half* __restrict__ kh,
    const __half* __restrict__ vv, __half* __restrict__ outh)
{
    extern __shared__ __half sm2[];
    __half* sqh = sm2;
    __half* skh = sqh + FA2_TILE;
    __half* sv  = skh + FA2_TILE;

    int tid = threadIdx.x, lane = tid & 31, wid = tid >> 5;
    int qt = gridDim.x - 1 - blockIdx.x;
    int bh = blockIdx.y;
    int b = bh >> 5, h = bh & 31, kvh = h >> 2;
    int q0 = qt * 64;

#pragma unroll
    for (int i = 0; i < 8; i++) {
        int c = tid + i * 128;
        int row = c >> 4;
        int col = (c & 15) * 8;
        size_t g = ((size_t)(b * SS + q0 + row) * NH + h) * HD + col;
        *(int4*)&sqh[row * FSTR + col] = *(const int4*)&qh[g];
    }

    float o[16][4];
#pragma unroll
    for (int n = 0; n < 16; n++)
#pragma unroll
        for (int j = 0; j < 4; j++) o[n][j] = 0.f;
    float m0 = -1e30f, m1 = -1e30f, l0 = 0.f, l1 = 0.f;

    int gr = lane >> 2, qc = (lane & 3) * 2;
    int arow = wid * 16 + (lane & 7) + ((lane >> 3) & 1) * 8;
    int acolo = ((lane >> 4) & 1) * 8;
    int brow = (lane & 7) + ((lane >> 4) & 1) * 8;
    int bcolo = ((lane >> 3) & 1) * 8;
    int vrow = (lane & 7) + ((lane >> 3) & 1) * 8;
    int vcolo = ((lane >> 4) & 1) * 8;

    for (int nt = 0; nt <= qt; nt++) {
        int k0 = nt * 64;
        __syncthreads();
#pragma unroll
        for (int i = 0; i < 8; i++) {
            int c = tid + i * 128;
            int row = c >> 4;
            int col = (c & 15) * 8;
            size_t g = ((size_t)(b * SS + k0 + row) * NKV + kvh) * HD + col;
            *(int4*)&skh[row * FSTR + col] = *(const int4*)&kh[g];
            *(int4*)&sv [row * FSTR + col] = *(const int4*)&vv[g];
        }
        __syncthreads();

        float s[8][4];
#pragma unroll
        for (int n = 0; n < 8; n++)
#pragma unroll
            for (int j = 0; j < 4; j++) s[n][j] = 0.f;

#pragma unroll
        for (int kc = 0; kc < 8; kc++) {
            u32 aH[4];
            ldsm4(aH[0], aH[1], aH[2], aH[3], &sqh[arow * FSTR + kc * 16 + acolo]);
            u32 bH[8][2];
#pragma unroll
            for (int p = 0; p < 4; p++) {
                u32 r0, r1, r2, r3;
                ldsm4(r0, r1, r2, r3, &skh[(p * 16 + brow) * FSTR + kc * 16 + bcolo]);
                bH[2 * p][0] = r0; bH[2 * p][1] = r1;
                bH[2 * p + 1][0] = r2; bH[2 * p + 1][1] = r3;
            }
#pragma unroll
            for (int n = 0; n < 8; n++) mma16816h(s[n], aH, bH[n]);
        }

        if (nt == qt) {
            int lr0 = wid * 16 + gr, lr1 = lr0 + 8;
#pragma unroll
            for (int n = 0; n < 8; n++) {
                int lc = n * 8 + qc;
                if (lc     > lr0) s[n][0] = -1e30f;
                if (lc + 1 > lr0) s[n][1] = -1e30f;
                if (lc     > lr1) s[n][2] = -1e30f;
                if (lc + 1 > lr1) s[n][3] = -1e30f;
            }
        }

        float mx0 = -1e30f, mx1 = -1e30f;
#pragma unroll
        for (int n = 0; n < 8; n++) {
            mx0 = fmaxf(mx0, fmaxf(s[n][0], s[n][1]));
            mx1 = fmaxf(mx1, fmaxf(s[n][2], s[n][3]));
        }
        mx0 = fmaxf(mx0, __shfl_xor_sync(0xffffffffu, mx0, 1));
        mx0 = fmaxf(mx0, __shfl_xor_sync(0xffffffffu, mx0, 2));
        mx1 = fmaxf(mx1, __shfl_xor_sync(0xffffffffu, mx1, 1));
        mx1 = fmaxf(mx1, __shfl_xor_sync(0xffffffffu, mx1, 2));
        float nm0 = fmaxf(m0, mx0), nm1 = fmaxf(m1, mx1);
        float a0 = fast_exp(m0 - nm0), a1 = fast_exp(m1 - nm1);
        m0 = nm0; m1 = nm1;

        float ls0 = 0.f, ls1 = 0.f;
        u32 pa[4][4];
#pragma unroll
        for (int n = 0; n < 8; n++) {
            float p0 = fast_exp(s[n][0] - nm0);
            float p1 = fast_exp(s[n][1] - nm0);
            float p2 = fast_exp(s[n][2] - nm1);
            float p3 = fast_exp(s[n][3] - nm1);
            ls0 += p0 + p1; ls1 += p2 + p3;
            __half2 hi = __floats2half2_rn(p0, p1);
            __half2 lo = __floats2half2_rn(p2, p3);
            int j = n >> 1;
            if ((n & 1) == 0) {
                pa[j][0] = *(u32*)&hi; pa[j][1] = *(u32*)&lo;
            } else {
                pa[j][2] = *(u32*)&hi; pa[j][3] = *(u32*)&lo;
            }
        }
        ls0 += __shfl_xor_sync(0xffffffffu, ls0, 1);
        ls0 += __shfl_xor_sync(0xffffffffu, ls0, 2);
        ls1 += __shfl_xor_sync(0xffffffffu, ls1, 1);
        ls1 += __shfl_xor_sync(0xffffffffu, ls1, 2);
        l0 = l0 * a0 + ls0;
        l1 = l1 * a1 + ls1;

#pragma unroll
        for (int n = 0; n < 16; n++) {
            o[n][0] *= a0; o[n][1] *= a0;
            o[n][2] *= a1; o[n][3] *= a1;
        }

#pragma unroll
        for (int np = 0; np < 8; np++) {
#pragma unroll
            for (int j = 0; j < 4; j++) {
                u32 r0, r1, r2, r3;
                ldsm4t(r0, r1, r2, r3, &sv[(j * 16 + vrow) * FSTR + np * 16 + vcolo]);
                u32 bv0[2] = {r0, r1};
                u32 bv1[2] = {r2, r3};
                mma16816h(o[2 * np],     pa[j], bv0);
                mma16816h(o[2 * np + 1], pa[j], bv1);
            }
        }
    }

    float inv0 = 1.f / l0, inv1 = 1.f / l1;
    int row0 = q0 + wid * 16 + gr;
#pragma unroll
    for (int n = 0; n < 16; n++) {
        int col = n * 8 + qc;
        size_t base0 = ((size_t)(b * SS + row0)     * NH + h) * HD + col;
        size_t base1 = ((size_t)(b * SS + row0 + 8) * NH + h) * HD + col;
        *(u32*)&outh[base0] = pack_h2(o[n][0] * inv0, o[n][1] * inv0);
        *(u32*)&outh[base1] = pack_h2(o[n][2] * inv1, o[n][3] * inv1);
    }
}

// ---------------------------------------------------------------------------
extern "C" void kernel_launch(void* const* d_in, const int* in_sizes, int n_in,
                              void* d_out, int out_size)
{
    const float* x   = (const float*)d_in[0];
    const float* wq  = (const float*)d_in[1];
    const float* wk  = (const float*)d_in[2];
    const float* wv  = (const float*)d_in[3];
    const float* wo  = (const float*)d_in[4];
    const float* fc  = (const float*)d_in[5];
    const float* fs  = (const float*)d_in[6];
    float* out = (float*)d_out;

    __half *xh, *wqf, *wkf, *wvf, *wof;
    cudaGetSymbolAddress((void**)&xh, g_xh);
    cudaGetSymbolAddress((void**)&wqf, g_wq);  cudaGetSymbolAddress((void**)&wkf, g_wk);
    cudaGetSymbolAddress((void**)&wvf, g_wv);  cudaGetSymbolAddress((void**)&wof, g_wo);
    __half *qhp, *khp, *vhp, *ahp;
    cudaGetSymbolAddress((void**)&qhp, g_qh);  cudaGetSymbolAddress((void**)&khp, g_kh);
    cudaGetSymbolAddress((void**)&vhp, g_vh);  cudaGetSymbolAddress((void**)&ahp, g_ah);

    cudaFuncSetAttribute(gemm_qkv, cudaFuncAttributeMaxDynamicSharedMemorySize, GEMM_SMEM);
    cudaFuncSetAttribute(gemm_wo, cudaFuncAttributeMaxDynamicSharedMemorySize, GEMM_SMEM);
    cudaFuncSetAttribute(flash_mma, cudaFuncAttributeMaxDynamicSharedMemorySize, FA2_SMEM);

    // prep: all weights + x -> fp16
    size_t total = 2 * (size_t)DIM * DIM + 2 * (size_t)KVDIM * DIM + (size_t)M_TOK * DIM;
    prep_half<<<(unsigned)(total / 16 / 256), 256>>>(wq, wk, wv, wo, x,
                                                     wqf, wkf, wvf, wof, xh);

    // fused QKV projection + RoPE (q, k, v all fp16)
    dim3 gqkv(48, M_TOK / 128);
    gemm_qkv<<<gqkv, 256, GEMM_SMEM>>>(xh, wqf, wkf, wvf, qhp, khp, vhp, fc, fs);

    // attention (single-pass S, BM=64, fp16 out)
    dim3 ga(SS / 64, BB * NH);
    flash_mma<<<ga, 128, FA2_SMEM>>>(qhp, khp, vhp, ahp);

    // output projection
    dim3 gq(DIM / 128, M_TOK / 128);
    gemm_wo<<<gq, 256, GEMM_SMEM>>>(ahp, wof, out, DIM, DIM);
}